// round 9
// baseline (speedup 1.0000x reference)
#include <cuda_runtime.h>

#define NTAG  9
#define SEQ   512
#define BATCH 4096
#define WPC   4                    // warps per CTA
#define GPW   3                    // active 9-lane groups per warp (padded to 4 in smem)
#define SPG   2                    // sequences per group (ILP-2)
#define SEQ_PER_WARP (GPW * SPG)   // 6
#define NWARP ((BATCH + SEQ_PER_WARP - 1) / SEQ_PER_WARP)   // 683
#define NCTA  ((NWARP + WPC - 1) / WPC)                     // 171

// ---- device scratch (globals: allocation-free) ----
__device__ int    g_len[BATCH];
__device__ int    g_hist[SEQ + 1];      // zero-init BSS; re-zeroed by prefix kernel
__device__ int    g_binoff[SEQ + 1];
__device__ int    g_perm[BATCH];
__device__ double g_pacc[NCTA];
__device__ int    g_pchars[NCTA];

// ============ 1) lengths + histogram (warp per sequence) ============
__global__ void __launch_bounds__(128) crf_len_hist(const int* __restrict__ mask)
{
    const int lane = threadIdx.x & 31;
    const int seq  = blockIdx.x * 4 + (threadIdx.x >> 5);
    const int4* m4 = reinterpret_cast<const int4*>(mask + (size_t)seq * SEQ);
    int s = 0;
#pragma unroll
    for (int k = 0; k < 4; k++) {
        int4 v = m4[lane + 32 * k];
        s += v.x + v.y + v.z + v.w;
    }
#pragma unroll
    for (int o = 16; o; o >>= 1) s += __shfl_xor_sync(0xffffffffu, s, o);
    if (lane == 0) {
        g_len[seq] = s;
        atomicAdd(&g_hist[s], 1);
    }
}

// ============ 2) exclusive prefix over hist -> binoff; re-zero hist ============
__global__ void __launch_bounds__(512) crf_prefix()
{
    __shared__ int a[512], b[512];
    const int tid = threadIdx.x;
    a[tid] = g_hist[tid];
    __syncthreads();
    int* src = a; int* dst = b;
#pragma unroll
    for (int off = 1; off < 512; off <<= 1) {
        dst[tid] = (tid >= off) ? src[tid] + src[tid - off] : src[tid];
        __syncthreads();
        int* t = src; src = dst; dst = t;
    }
    g_binoff[tid + 1] = src[tid];
    if (tid == 0) g_binoff[0] = 0;
    g_hist[tid] = 0;
    if (tid == 0) g_hist[512] = 0;
}

// ============ 3) scatter: counting-sort permutation by length ============
__global__ void __launch_bounds__(128) crf_scatter()
{
    const int bseq = blockIdx.x * 128 + threadIdx.x;
    const int L    = g_len[bseq];
    const int slot = atomicAdd(&g_binoff[L], 1);
    g_perm[slot] = bseq;
}

// ============ 4) main scan: 6 length-adjacent seqs/warp (3 groups x ILP-2),
//               smem (LDS) broadcast, double-buffered by parity ============
__global__ void __launch_bounds__(128) crf_scan(
    const float* __restrict__ bert,  // [B, S, 9] f32
    const int* __restrict__ tags,    // [B, S] i32
    const float* __restrict__ trans) // [11, 11] f32
{
    __shared__ float  sT[121];
    // Group axis padded to 4: idle lanes (g==3, gj=36..47) write into dead
    // padding instead of overflowing. 16B-aligned base for float4 broadcasts.
    // Strides: group 48B, seq 192B, parity 384B, warp 768B - all 16B multiples.
    __shared__ __align__(16) float sW[WPC][2][SPG][4 * 12];
    __shared__ double sAcc;
    __shared__ int    sChars;

    const int tid = threadIdx.x;
    if (tid < 121) sT[tid] = trans[tid];
    if (tid == 0) { sAcc = 0.0; sChars = 0; }
    __syncthreads();

    const int lane  = tid & 31;
    const int wid   = tid >> 5;
    const int g     = lane / 9;            // group 0..2 active, 3 = idle lanes
    const int j     = lane - g * 9;        // tag owned by this lane
    const int gbase = g * 9;
    const int gj    = g * 12 + j;          // max 36+4=40 < 48: stays in padding

    // warp -> 6 consecutive sorted slots; CTAs take strided warps for SM balance
    const int gw    = wid * NCTA + blockIdx.x;           // 0..683
    const int slotA = 6 * gw + 2 * g;
    const int slotB = slotA + 1;
    const bool vg     = (g < 3);
    const bool validA = vg && (slotA < BATCH);
    const bool validB = vg && (slotB < BATCH);
    const int  seqA   = validA ? g_perm[slotA] : 0;
    const int  seqB   = validB ? g_perm[slotB] : 0;
    const int  LA     = validA ? g_len[seqA] : 0;
    const int  LB     = validB ? g_len[seqB] : 0;

    const float* emA = bert + (size_t)seqA * (SEQ * NTAG);
    const float* emB = bert + (size_t)seqB * (SEQ * NTAG);
    const int*   tgA = tags + (size_t)seqA * SEQ;
    const int*   tgB = tags + (size_t)seqB * SEQ;

    // E column for this lane + end factor
    float E[NTAG];
#pragma unroll
    for (int i = 0; i < NTAG; i++) E[i] = __expf(sT[i * 11 + j]);
    const float Eend = __expf(sT[j * 11 + 10]);

    int maxL = max(LA, LB);
#pragma unroll
    for (int o = 16; o; o >>= 1) maxL = max(maxL, __shfl_xor_sync(0xffffffffu, maxL, o));

    // ---- t = 0 ----
    const float em0A = __ldg(emA + j);
    const float em0B = __ldg(emB + j);
    float WA = __expf(sT[99 + j] + em0A);
    float WB = __expf(sT[99 + j] + em0B);
    int eAccA = 0, eAccB = 0;
    const int tag0A = __ldg(tgA);
    const int tag0B = __ldg(tgB);
    float raccA = (tag0A == j) ? em0A : 0.0f;   // per-lane emit accumulation
    float raccB = (tag0B == j) ? em0B : 0.0f;
    float rtrA = 0.0f, rtrB = 0.0f;             // leader-lane transition sums
    if (j == 0) { rtrA = sT[99 + tag0A]; rtrB = sT[99 + tag0B]; }
    int prevA = tag0A, prevB = tag0B;

    // seed parity-1 buffers (read by t = 1)
    sW[wid][1][0][gj] = WA;
    sW[wid][1][1][gj] = WB;

    // ---- depth-2 rotating prefetch: slot (t&1) holds row t ----
    float epA[2], epB[2];
    int   tpA[2], tpB[2];
    epA[1] = __ldg(emA + 1 * NTAG + j);  tpA[1] = __ldg(tgA + 1);
    epB[1] = __ldg(emB + 1 * NTAG + j);  tpB[1] = __ldg(tgB + 1);
    {
        const int t2 = min(2, SEQ - 1);
        epA[0] = __ldg(emA + t2 * NTAG + j);  tpA[0] = __ldg(tgA + t2);
        epB[0] = __ldg(emB + t2 * NTAG + j);  tpB[0] = __ldg(tgB + t2);
    }

#pragma unroll 2
    for (int t = 1; t < maxL; ++t) {
        __syncwarp();
        const int par = t & 1;

        // broadcast reads (conflict-free; idle lanes read padding - harmless)
        const float* bA = &sW[wid][par][0][g * 12];
        const float* bB = &sW[wid][par][1][g * 12];
        const float4 a0 = reinterpret_cast<const float4*>(bA)[0];
        const float4 a1 = reinterpret_cast<const float4*>(bA)[1];
        const float  a8 = bA[8];
        const float4 b0 = reinterpret_cast<const float4*>(bB)[0];
        const float4 b1 = reinterpret_cast<const float4*>(bB)[1];
        const float  b8 = bB[8];

        // consume row t, then refill slot with row t+2
        const float emvA = epA[par], emvB = epB[par];
        const int   tagA = tpA[par], tagB = tpB[par];
        const int   tpre = min(t + 2, SEQ - 1);
        epA[par] = __ldg(emA + tpre * NTAG + j);  tpA[par] = __ldg(tgA + tpre);
        epB[par] = __ldg(emB + tpre * NTAG + j);  tpB[par] = __ldg(tgB + tpre);

        // matvec trees
        float xA0 = a0.x * E[0], xA1 = a0.y * E[1], xA2 = a0.z * E[2];
        xA0 = fmaf(a0.w, E[3], xA0); xA1 = fmaf(a1.x, E[4], xA1); xA2 = fmaf(a1.y, E[5], xA2);
        xA0 = fmaf(a1.z, E[6], xA0); xA1 = fmaf(a1.w, E[7], xA1); xA2 = fmaf(a8,   E[8], xA2);
        float accA = xA0 + xA1 + xA2;

        float xB0 = b0.x * E[0], xB1 = b0.y * E[1], xB2 = b0.z * E[2];
        xB0 = fmaf(b0.w, E[3], xB0); xB1 = fmaf(b1.x, E[4], xB1); xB2 = fmaf(b1.y, E[5], xB2);
        xB0 = fmaf(b1.z, E[6], xB0); xB1 = fmaf(b1.w, E[7], xB1); xB2 = fmaf(b8,   E[8], xB2);
        float accB = xB0 + xB1 + xB2;

        const float XA = __expf(emvA);
        const float XB = __expf(emvB);
        const bool actA = (t < LA);
        const bool actB = (t < LB);

        // exact power-of-2 rescale every 4 steps (from the read values)
        if ((t & 3) == 0) {
            float mA = fmaxf(fmaxf(fmaxf(a0.x, a0.y), fmaxf(a0.z, a0.w)),
                             fmaxf(fmaxf(a1.x, a1.y), fmaxf(a1.z, fmaxf(a1.w, a8))));
            const int eA = ((__float_as_int(mA) >> 23) & 255) - 127;
            accA *= __int_as_float((127 - eA) << 23);
            if (actA) eAccA += eA;

            float mB = fmaxf(fmaxf(fmaxf(b0.x, b0.y), fmaxf(b0.z, b0.w)),
                             fmaxf(fmaxf(b1.x, b1.y), fmaxf(b1.z, fmaxf(b1.w, b8))));
            const int eB = ((__float_as_int(mB) >> 23) & 255) - 127;
            accB *= __int_as_float((127 - eB) << 23);
            if (actB) eAccB += eB;
        }

        if (actA) {
            WA = accA * XA;
            if (tagA == j) raccA += emvA;
            if (j == 0) { rtrA += sT[prevA * 11 + tagA]; prevA = tagA; }
        }
        if (actB) {
            WB = accB * XB;
            if (tagB == j) raccB += emvB;
            if (j == 0) { rtrB += sT[prevB * 11 + tagB]; prevB = tagB; }
        }

        // publish for next iteration (other parity); idle lanes hit padding
        sW[wid][par ^ 1][0][gj] = WA;
        sW[wid][par ^ 1][1][gj] = WB;
    }

    // ---- termination: group reductions via one-shot shfl ----
    const float vA = WA * Eend;
    const float vB = WB * Eend;
    float svA = 0.0f, svB = 0.0f, srA = 0.0f, srB = 0.0f;
#pragma unroll
    for (int i = 0; i < NTAG; i++) {
        const int src = (gbase + i) & 31;
        svA += __shfl_sync(0xffffffffu, vA,    src);
        svB += __shfl_sync(0xffffffffu, vB,    src);
        srA += __shfl_sync(0xffffffffu, raccA, src);
        srB += __shfl_sync(0xffffffffu, raccB, src);
    }

    if (j == 0 && vg) {
        double contrib = 0.0;
        int chars = 0;
        if (validA) {
            const float realA = rtrA + srA + sT[prevA * 11 + 10];
            contrib += (double)eAccA * 0.6931471805599453 + (double)__logf(svA) - (double)realA;
            chars += LA;
        }
        if (validB) {
            const float realB = rtrB + srB + sT[prevB * 11 + 10];
            contrib += (double)eAccB * 0.6931471805599453 + (double)__logf(svB) - (double)realB;
            chars += LB;
        }
        if (chars) {
            atomicAdd(&sAcc, contrib);
            atomicAdd(&sChars, chars);
        }
    }
    __syncthreads();
    if (tid == 0) {
        g_pacc[blockIdx.x]   = sAcc;
        g_pchars[blockIdx.x] = sChars;
    }
}

// ============ 5) final reduction ============
__global__ void __launch_bounds__(128) crf_fin(float* out)
{
    __shared__ double    sa[128];
    __shared__ long long sc[128];
    const int tid = threadIdx.x;
    double a = 0.0; long long c = 0;
    for (int i = tid; i < NCTA; i += 128) {
        a += g_pacc[i];
        c += (long long)g_pchars[i];
    }
    sa[tid] = a; sc[tid] = c;
    __syncthreads();
    for (int o = 64; o; o >>= 1) {
        if (tid < o) { sa[tid] += sa[tid + o]; sc[tid] += sc[tid + o]; }
        __syncthreads();
    }
    if (tid == 0) out[0] = (float)(sa[0] / (double)sc[0]);
}

extern "C" void kernel_launch(void* const* d_in, const int* in_sizes, int n_in,
                              void* d_out, int out_size)
{
    const float* bert  = (const float*)d_in[0];
    const int*   mask  = (const int*)d_in[1];
    const int*   tags  = (const int*)d_in[2];
    const float* trans = (const float*)d_in[3];
    float* out = (float*)d_out;

    crf_len_hist<<<BATCH / 4, 128>>>(mask);
    crf_prefix<<<1, 512>>>();
    crf_scatter<<<BATCH / 128, 128>>>();
    crf_scan<<<NCTA, 128>>>(bert, tags, trans);
    crf_fin<<<1, 128>>>(out);
}

// round 10
// speedup vs baseline: 1.0721x; 1.0721x over previous
#include <cuda_runtime.h>

#define NTAG  9
#define SEQ   512
#define BATCH 4096
#define CL    32                  // chunk length
#define WARM  8                   // warmup steps (direction error ~0.1^8)
#define NCHUNK (SEQ / CL)         // 16
#define NPART  (32 * NCHUNK)      // 512 partial slots (grid.x * grid.y)

// ---- device scratch (globals: allocation-free) ----
__device__ int    g_len[BATCH];
__device__ int    g_hist[SEQ + 1];      // zero-init BSS; re-zeroed by prefix kernel
__device__ int    g_binoff[SEQ + 1];
__device__ int    g_perm[BATCH];
__device__ double g_pacc[NPART];

// ============ 1) lengths + histogram (warp per sequence) ============
__global__ void __launch_bounds__(128) crf_len_hist(const int* __restrict__ mask)
{
    const int lane = threadIdx.x & 31;
    const int seq  = blockIdx.x * 4 + (threadIdx.x >> 5);
    const int4* m4 = reinterpret_cast<const int4*>(mask + (size_t)seq * SEQ);
    int s = 0;
#pragma unroll
    for (int k = 0; k < 4; k++) {
        int4 v = m4[lane + 32 * k];
        s += v.x + v.y + v.z + v.w;
    }
#pragma unroll
    for (int o = 16; o; o >>= 1) s += __shfl_xor_sync(0xffffffffu, s, o);
    if (lane == 0) {
        g_len[seq] = s;
        atomicAdd(&g_hist[s], 1);
    }
}

// ============ 2) exclusive prefix over hist -> binoff; re-zero hist ============
__global__ void __launch_bounds__(512) crf_prefix()
{
    __shared__ int a[512], b[512];
    const int tid = threadIdx.x;
    a[tid] = g_hist[tid];
    __syncthreads();
    int* src = a; int* dst = b;
#pragma unroll
    for (int off = 1; off < 512; off <<= 1) {
        dst[tid] = (tid >= off) ? src[tid] + src[tid - off] : src[tid];
        __syncthreads();
        int* t = src; src = dst; dst = t;
    }
    g_binoff[tid + 1] = src[tid];
    if (tid == 0) g_binoff[0] = 0;
    g_hist[tid] = 0;
    if (tid == 0) g_hist[512] = 0;
}

// ============ 3) scatter: counting-sort permutation by length ============
__global__ void __launch_bounds__(128) crf_scatter()
{
    const int bseq = blockIdx.x * 128 + threadIdx.x;
    const int L    = g_len[bseq];
    const int slot = atomicAdd(&g_binoff[L], 1);
    g_perm[slot] = bseq;
}

// ============ 4) chunked scan: one (sequence, chunk) task per LANE.
//  Chunk c>0 starts from a uniform vector WARM steps early; Birkhoff
//  contraction (kappa ~ 0.1/step) makes the direction exact to ~1e-8 by the
//  chunk start. Chunk outputs telescope: sum_c r_c = log S(alpha_{L-1}).
//  grid = (32, 16): blockIdx.x covers 128 sorted slots, blockIdx.y = chunk.
__global__ void __launch_bounds__(128) crf_scan(
    const float* __restrict__ bert,  // [B, S, 9] f32
    const int* __restrict__ tags,    // [B, S] i32
    const float* __restrict__ trans) // [11, 11] f32
{
    __shared__ float  sT[121];
    __shared__ double sAcc;

    const int tid = threadIdx.x;
    if (tid < 121) sT[tid] = trans[tid];
    if (tid == 0) sAcc = 0.0;
    __syncthreads();

    const int c    = blockIdx.y;               // chunk id (CTA-uniform)
    const int slot = blockIdx.x * 128 + tid;   // sorted slot
    const int seq  = g_perm[slot];
    const int L    = g_len[seq];
    const int s    = c * CL;
    const bool act = (s < L);

    const float* em = bert + (size_t)seq * (SEQ * NTAG);
    const int*   tg = tags + (size_t)seq * SEQ;

    // E = exp(T[:9,:9]) fully register-resident
    float E[NTAG][NTAG];
#pragma unroll
    for (int i = 0; i < NTAG; i++)
#pragma unroll
        for (int j = 0; j < NTAG; j++)
            E[i][j] = __expf(sT[i * 11 + j]);

    float W[NTAG];
    float row[NTAG];
    int   tA = 0, tB = 0, gs = 0, prev = 0;
    int   eAcc = 0, eRef = 0;
    float SRef = 0.0f, rg = 0.0f;

    if (act) {
        if (c == 0) {
            // exact init at t = 0
#pragma unroll
            for (int j = 0; j < NTAG; j++) {
                const float e0 = __ldg(em + j);
                W[j] = __expf(sT[99 + j] + e0);
            }
            prev = __ldg(tg);
            rg   = sT[99 + prev] + __ldg(em + prev);   // first_trans + emit0
            tA = 1; gs = 1;
        } else {
            // uniform init WARM steps before the window
#pragma unroll
            for (int j = 0; j < NTAG; j++) W[j] = 1.0f;
            prev = __ldg(tg + s - 1);
            tA = s - WARM; gs = s;
        }
        tB = min(s + CL, L);
        // prologue row load (row tA)
#pragma unroll
        for (int j = 0; j < NTAG; j++) row[j] = __ldg(em + tA * NTAG + j);
    }

    for (int t = tA; t < tB; ++t) {
        // prefetch row t+1 (clamped) while computing with row t
        const int tn = min(t + 1, SEQ - 1);
        float rn[NTAG];
#pragma unroll
        for (int j = 0; j < NTAG; j++) rn[j] = __ldg(em + tn * NTAG + j);

        // alpha update in probability domain: W'_j = (sum_i W_i E_ij) * exp(em_tj)
        float nw[NTAG];
#pragma unroll
        for (int j = 0; j < NTAG; j++) {
            float a = W[0] * E[0][j];
#pragma unroll
            for (int i = 1; i < NTAG; i++) a = fmaf(W[i], E[i][j], a);
            nw[j] = a * __expf(row[j]);
        }
#pragma unroll
        for (int j = 0; j < NTAG; j++) W[j] = nw[j];

        // exact power-of-2 rescale every 4 steps
        if ((t & 3) == 0) {
            float mx = W[0];
#pragma unroll
            for (int j = 1; j < NTAG; j++) mx = fmaxf(mx, W[j]);
            const int e = ((__float_as_int(mx) >> 23) & 255) - 127;
            eAcc += e;
            const float sc = __int_as_float((127 - e) << 23);
#pragma unroll
            for (int j = 0; j < NTAG; j++) W[j] *= sc;
        }

        // reference point: end of warmup (c >= 1 only; t == s-1 never hits c==0)
        if (t == s - 1) {
            eRef = eAcc;
            float ss = W[0];
#pragma unroll
            for (int j = 1; j < NTAG; j++) ss += W[j];
            SRef = __logf(ss);
        }

        // gold path inside the window
        if (t >= gs) {
            const int tag = __ldg(tg + t);
            rg += sT[prev * 11 + tag] + __ldg(em + t * NTAG + tag);
            prev = tag;
        }

#pragma unroll
        for (int j = 0; j < NTAG; j++) row[j] = rn[j];
    }

    double contrib = 0.0;
    if (act) {
        const bool last = (L <= s + CL);       // this chunk reaches t = L-1
        float r;
        if (last) {
            float fin = 0.0f;
#pragma unroll
            for (int j = 0; j < NTAG; j++)
                fin = fmaf(W[j], __expf(sT[j * 11 + 10]), fin);
            r  = 0.6931472f * (float)(eAcc - eRef) + __logf(fin) - SRef;
            rg += sT[prev * 11 + 10];          // T[last_tag, end]
        } else {
            float ss = W[0];
#pragma unroll
            for (int j = 1; j < NTAG; j++) ss += W[j];
            r = 0.6931472f * (float)(eAcc - eRef) + __logf(ss) - SRef;
        }
        contrib = (double)r - (double)rg;
    }

    // warp reduce -> one smem atomic per warp -> one global slot per CTA
#pragma unroll
    for (int o = 16; o; o >>= 1)
        contrib += __shfl_down_sync(0xffffffffu, contrib, o);
    if ((tid & 31) == 0) atomicAdd(&sAcc, contrib);
    __syncthreads();
    if (tid == 0) g_pacc[blockIdx.y * 32 + blockIdx.x] = sAcc;
}

// ============ 5) final reduction: sum partials + num_chars from g_len ============
__global__ void __launch_bounds__(128) crf_fin(float* out)
{
    __shared__ double    sa[128];
    __shared__ long long sc[128];
    const int tid = threadIdx.x;
    double a = 0.0;
    long long ch = 0;
    for (int i = tid; i < NPART; i += 128) a += g_pacc[i];
    for (int i = tid; i < BATCH; i += 128) ch += (long long)g_len[i];
    sa[tid] = a; sc[tid] = ch;
    __syncthreads();
    for (int o = 64; o; o >>= 1) {
        if (tid < o) { sa[tid] += sa[tid + o]; sc[tid] += sc[tid + o]; }
        __syncthreads();
    }
    if (tid == 0) out[0] = (float)(sa[0] / (double)sc[0]);
}

extern "C" void kernel_launch(void* const* d_in, const int* in_sizes, int n_in,
                              void* d_out, int out_size)
{
    const float* bert  = (const float*)d_in[0];
    const int*   mask  = (const int*)d_in[1];
    const int*   tags  = (const int*)d_in[2];
    const float* trans = (const float*)d_in[3];
    float* out = (float*)d_out;

    crf_len_hist<<<BATCH / 4, 128>>>(mask);
    crf_prefix<<<1, 512>>>();
    crf_scatter<<<BATCH / 128, 128>>>();
    dim3 grid(32, NCHUNK);
    crf_scan<<<grid, 128>>>(bert, tags, trans);
    crf_fin<<<1, 128>>>(out);
}

// round 11
// speedup vs baseline: 2.2579x; 2.1060x over previous
#include <cuda_runtime.h>

#define NTAG  9
#define SEQ   512
#define BATCH 4096
#define CL    32                  // chunk length
#define WARM  8                   // warmup steps (direction error ~0.1^8)
#define NCHUNK (SEQ / CL)         // 16
#define NPART  (32 * NCHUNK)      // 512 partial slots

// ---- device scratch (globals: allocation-free) ----
__device__ int    g_len[BATCH];
__device__ int    g_hist[SEQ + 1];      // zero-init BSS; re-zeroed by prefix kernel
__device__ int    g_binoff[SEQ + 1];
__device__ int    g_perm[BATCH];
__device__ double g_pacc[NPART];

// ============ 1) lengths + histogram (warp per sequence) ============
__global__ void __launch_bounds__(128) crf_len_hist(const int* __restrict__ mask)
{
    const int lane = threadIdx.x & 31;
    const int seq  = blockIdx.x * 4 + (threadIdx.x >> 5);
    const int4* m4 = reinterpret_cast<const int4*>(mask + (size_t)seq * SEQ);
    int s = 0;
#pragma unroll
    for (int k = 0; k < 4; k++) {
        int4 v = m4[lane + 32 * k];
        s += v.x + v.y + v.z + v.w;
    }
#pragma unroll
    for (int o = 16; o; o >>= 1) s += __shfl_xor_sync(0xffffffffu, s, o);
    if (lane == 0) {
        g_len[seq] = s;
        atomicAdd(&g_hist[s], 1);
    }
}

// ============ 2) exclusive prefix over hist -> binoff; re-zero hist ============
__global__ void __launch_bounds__(512) crf_prefix()
{
    __shared__ int a[512], b[512];
    const int tid = threadIdx.x;
    a[tid] = g_hist[tid];
    __syncthreads();
    int* src = a; int* dst = b;
#pragma unroll
    for (int off = 1; off < 512; off <<= 1) {
        dst[tid] = (tid >= off) ? src[tid] + src[tid - off] : src[tid];
        __syncthreads();
        int* t = src; src = dst; dst = t;
    }
    g_binoff[tid + 1] = src[tid];
    if (tid == 0) g_binoff[0] = 0;
    g_hist[tid] = 0;
    if (tid == 0) g_hist[512] = 0;
}

// ============ 3) scatter: counting-sort permutation by length ============
__global__ void __launch_bounds__(128) crf_scatter()
{
    const int bseq = blockIdx.x * 128 + threadIdx.x;
    const int L    = g_len[bseq];
    const int slot = atomicAdd(&g_binoff[L], 1);
    g_perm[slot] = bseq;
}

// ============ 4) chunked scan, one (sequence, chunk) per LANE.
//  All loads vectorized: 4 rows (144B, 16B-aligned at t0%4==0) as 9 LDG.128,
//  tags as int4; gold-path emit selected from quad registers (no L1 traffic).
//  Double-buffered quads overlap the next load with current compute.
__global__ void __launch_bounds__(128) crf_scan(
    const float* __restrict__ bert,  // [B, S, 9] f32
    const int* __restrict__ tags,    // [B, S] i32
    const float* __restrict__ trans) // [11, 11] f32
{
    __shared__ float  sT[121];
    __shared__ double sAcc;

    const int tid = threadIdx.x;
    if (tid < 121) sT[tid] = trans[tid];
    if (tid == 0) sAcc = 0.0;
    __syncthreads();

    const int c    = blockIdx.y;               // chunk id
    const int slot = blockIdx.x * 128 + tid;   // sorted slot
    const int seq  = g_perm[slot];
    const int L    = g_len[seq];
    const int s    = c * CL;
    const bool act = (s < L);

    const float* em = bert + (size_t)seq * (SEQ * NTAG);
    const int*   tg = tags + (size_t)seq * SEQ;

    // E = exp(T[:9,:9]) register-resident
    float E[NTAG][NTAG];
#pragma unroll
    for (int i = 0; i < NTAG; i++)
#pragma unroll
        for (int j = 0; j < NTAG; j++)
            E[i][j] = __expf(sT[i * 11 + j]);

    float W[NTAG];
    int   eAcc = 0, eRef = 0, prev = 0;
    float SRef = 0.0f, rg = 0.0f;
    int   t0s = 0, tB = 0, gs = 0;

    if (act) {
        tB = min(s + CL, L);
        if (c == 0) {
            t0s = 0; gs = 1;          // W initialized at t=0 inside the loop
        } else {
            t0s = s - WARM; gs = s;   // uniform start, WARM steps early
#pragma unroll
            for (int j = 0; j < NTAG; j++) W[j] = 1.0f;
            prev = __ldg(tg + s - 1);
        }
    }

    // double-buffered quad: buf[pb][4*j + r] = em[(t0+r)*9 + j]
    float buf[2][36];
    auto ldquad = [&](int t0, int pb) {
        const float4* p = reinterpret_cast<const float4*>(em + t0 * NTAG);
#pragma unroll
        for (int k = 0; k < 9; k++) {
            const float4 v = __ldg(p + k);
            buf[pb][4 * k + 0] = v.x;
            buf[pb][4 * k + 1] = v.y;
            buf[pb][4 * k + 2] = v.z;
            buf[pb][4 * k + 3] = v.w;
        }
    };

    if (act) ldquad(t0s, 0);

    int pb = 0;
    for (int t0 = t0s; t0 < tB; t0 += 4, pb ^= 1) {
        if (t0 + 4 < tB) ldquad(t0 + 4, pb ^ 1);          // prefetch next quad
        const int4 tq = *reinterpret_cast<const int4*>(tg + t0);  // 16B-aligned
        const int tags4[4] = {tq.x, tq.y, tq.z, tq.w};
        const float* bq = buf[pb];

#pragma unroll
        for (int r = 0; r < 4; r++) {
            const int t = t0 + r;
            if (t < tB) {
                if (t == 0) {
                    // exact init (c == 0 only)
#pragma unroll
                    for (int j = 0; j < NTAG; j++)
                        W[j] = __expf(sT[99 + j] + bq[4 * j + 0]);
                    prev = tags4[0];
                    float ev = bq[0];
#pragma unroll
                    for (int j = 1; j < NTAG; j++)
                        if (prev == j) ev = bq[4 * j + 0];
                    rg = sT[99 + prev] + ev;
                } else {
                    // alpha update: W'_j = (sum_i W_i E_ij) * exp(em_tj)
                    float nw[NTAG];
#pragma unroll
                    for (int j = 0; j < NTAG; j++) {
                        float a = W[0] * E[0][j];
#pragma unroll
                        for (int i = 1; i < NTAG; i++) a = fmaf(W[i], E[i][j], a);
                        nw[j] = a * __expf(bq[4 * j + r]);
                    }

                    // exact power-of-2 rescale at t % 4 == 0 (r == 0 quads)
                    if (r == 0) {
                        float mx = nw[0];
#pragma unroll
                        for (int j = 1; j < NTAG; j++) mx = fmaxf(mx, nw[j]);
                        const int e = ((__float_as_int(mx) >> 23) & 255) - 127;
                        eAcc += e;
                        const float sc = __int_as_float((127 - e) << 23);
#pragma unroll
                        for (int j = 0; j < NTAG; j++) nw[j] *= sc;
                    }
#pragma unroll
                    for (int j = 0; j < NTAG; j++) W[j] = nw[j];

                    // reference point at end of warmup (c >= 1 only)
                    if (t == s - 1) {
                        eRef = eAcc;
                        float ss = W[0];
#pragma unroll
                        for (int j = 1; j < NTAG; j++) ss += W[j];
                        SRef = __logf(ss);
                    }

                    // gold path inside the window; emit from quad registers
                    if (t >= gs) {
                        const int tag = tags4[r];
                        float ev = bq[r];
#pragma unroll
                        for (int j = 1; j < NTAG; j++)
                            if (tag == j) ev = bq[4 * j + r];
                        rg += sT[prev * 11 + tag] + ev;
                        prev = tag;
                    }
                }
            }
        }
    }

    double contrib = 0.0;
    if (act) {
        const bool last = (L <= s + CL);       // chunk reaches t = L-1
        float r;
        if (last) {
            float fin = 0.0f;
#pragma unroll
            for (int j = 0; j < NTAG; j++)
                fin = fmaf(W[j], __expf(sT[j * 11 + 10]), fin);
            r  = 0.6931472f * (float)(eAcc - eRef) + __logf(fin) - SRef;
            rg += sT[prev * 11 + 10];
        } else {
            float ss = W[0];
#pragma unroll
            for (int j = 1; j < NTAG; j++) ss += W[j];
            r = 0.6931472f * (float)(eAcc - eRef) + __logf(ss) - SRef;
        }
        contrib = (double)r - (double)rg;
    }

    // warp reduce -> smem -> one global slot per CTA
#pragma unroll
    for (int o = 16; o; o >>= 1)
        contrib += __shfl_down_sync(0xffffffffu, contrib, o);
    if ((tid & 31) == 0) atomicAdd(&sAcc, contrib);
    __syncthreads();
    if (tid == 0) g_pacc[blockIdx.y * 32 + blockIdx.x] = sAcc;
}

// ============ 5) final reduction: partials + num_chars from g_len ============
__global__ void __launch_bounds__(128) crf_fin(float* out)
{
    __shared__ double    sa[128];
    __shared__ long long sc[128];
    const int tid = threadIdx.x;
    double a = 0.0;
    long long ch = 0;
    for (int i = tid; i < NPART; i += 128) a += g_pacc[i];
    for (int i = tid; i < BATCH; i += 128) ch += (long long)g_len[i];
    sa[tid] = a; sc[tid] = ch;
    __syncthreads();
    for (int o = 64; o; o >>= 1) {
        if (tid < o) { sa[tid] += sa[tid + o]; sc[tid] += sc[tid + o]; }
        __syncthreads();
    }
    if (tid == 0) out[0] = (float)(sa[0] / (double)sc[0]);
}

extern "C" void kernel_launch(void* const* d_in, const int* in_sizes, int n_in,
                              void* d_out, int out_size)
{
    const float* bert  = (const float*)d_in[0];
    const int*   mask  = (const int*)d_in[1];
    const int*   tags  = (const int*)d_in[2];
    const float* trans = (const float*)d_in[3];
    float* out = (float*)d_out;

    crf_len_hist<<<BATCH / 4, 128>>>(mask);
    crf_prefix<<<1, 512>>>();
    crf_scatter<<<BATCH / 128, 128>>>();
    dim3 grid(32, NCHUNK);
    crf_scan<<<grid, 128>>>(bert, tags, trans);
    crf_fin<<<1, 128>>>(out);
}

// round 12
// speedup vs baseline: 3.2908x; 1.4575x over previous
#include <cuda_runtime.h>

#define NTAG  9
#define SEQ   512
#define BATCH 4096
#define CL    32                  // chunk length
#define WARM  8                   // warmup steps (direction error ~0.1^8)
#define NCHUNK (SEQ / CL)         // 16
#define NPART  (32 * NCHUNK)      // 512 partial slots
#define STAGES 3
#define STAGEF (128 * 36)         // floats per stage
#define DSMEM  (STAGES * STAGEF * 4)   // 55296 bytes

// ---- device scratch (globals: allocation-free) ----
__device__ int    g_len[BATCH];
__device__ int    g_hist[SEQ + 1];      // zero-init BSS; re-zeroed by prefix kernel
__device__ int    g_binoff[SEQ + 1];
__device__ int    g_perm[BATCH];
__device__ double g_pacc[NPART];

// ============ 1) lengths + histogram (warp per sequence) ============
__global__ void __launch_bounds__(128) crf_len_hist(const int* __restrict__ mask)
{
    const int lane = threadIdx.x & 31;
    const int seq  = blockIdx.x * 4 + (threadIdx.x >> 5);
    const int4* m4 = reinterpret_cast<const int4*>(mask + (size_t)seq * SEQ);
    int s = 0;
#pragma unroll
    for (int k = 0; k < 4; k++) {
        int4 v = m4[lane + 32 * k];
        s += v.x + v.y + v.z + v.w;
    }
#pragma unroll
    for (int o = 16; o; o >>= 1) s += __shfl_xor_sync(0xffffffffu, s, o);
    if (lane == 0) {
        g_len[seq] = s;
        atomicAdd(&g_hist[s], 1);
    }
}

// ============ 2) exclusive prefix over hist -> binoff; re-zero hist ============
__global__ void __launch_bounds__(512) crf_prefix()
{
    __shared__ int a[512], b[512];
    const int tid = threadIdx.x;
    a[tid] = g_hist[tid];
    __syncthreads();
    int* src = a; int* dst = b;
#pragma unroll
    for (int off = 1; off < 512; off <<= 1) {
        dst[tid] = (tid >= off) ? src[tid] + src[tid - off] : src[tid];
        __syncthreads();
        int* t = src; src = dst; dst = t;
    }
    g_binoff[tid + 1] = src[tid];
    if (tid == 0) g_binoff[0] = 0;
    g_hist[tid] = 0;
    if (tid == 0) g_hist[512] = 0;
}

// ============ 3) scatter: counting-sort permutation by length ============
__global__ void __launch_bounds__(128) crf_scatter()
{
    const int bseq = blockIdx.x * 128 + threadIdx.x;
    const int L    = g_len[bseq];
    const int slot = atomicAdd(&g_binoff[L], 1);
    g_perm[slot] = bseq;
}

// ============ 4) chunked scan, one (sequence, chunk) per LANE.
//  CTA-cooperative quad staging: thread-piece f = tid + 128k loads 16B of
//  sequence (f/9)'s quad -> consecutive lanes hit the same rows (4x fewer L1
//  wavefronts than per-lane scattered loads). cp.async 3-stage ring keeps 2
//  quads in flight; lanes read their own row-quad back via 9x LDS.128.
__global__ void __launch_bounds__(128, 3) crf_scan(
    const float* __restrict__ bert,  // [B, S, 9] f32
    const int* __restrict__ tags,    // [B, S] i32
    const float* __restrict__ trans) // [11, 11] f32
{
    extern __shared__ float dsm[];   // [STAGES][128][36]
    __shared__ float  sT[121];
    __shared__ int    sBase[128];
    __shared__ int    stB[128];
    __shared__ int    sMax[4];
    __shared__ double sAcc;

    const int tid = threadIdx.x;
    if (tid < 121) sT[tid] = trans[tid];
    if (tid == 0) sAcc = 0.0;

    const int c    = blockIdx.y;               // chunk id (CTA-uniform)
    const int slot = blockIdx.x * 128 + tid;   // sorted slot (grid.x*128 == BATCH)
    const int seq  = g_perm[slot];
    const int L    = g_len[seq];
    const int s    = c * CL;
    const bool act = (s < L);
    const int t0s  = (c == 0) ? 0 : s - WARM;  // CTA-uniform quad-aligned start
    const int tB   = act ? min(s + CL, L) : 0;

    sBase[tid] = seq * (SEQ * NTAG);
    stB[tid]   = tB;
    __syncthreads();

    // CTA max of tB -> uniform quad count
    {
        int m = tB;
#pragma unroll
        for (int o = 16; o; o >>= 1) m = max(m, __shfl_xor_sync(0xffffffffu, m, o));
        if ((tid & 31) == 0) sMax[tid >> 5] = m;
    }
    __syncthreads();
    const int maxtB = max(max(sMax[0], sMax[1]), max(sMax[2], sMax[3]));
    const int nq = (maxtB > t0s) ? ((maxtB - t0s + 3) >> 2) : 0;

    // E = exp(T[:9,:9]) register-resident
    float E[NTAG][NTAG];
#pragma unroll
    for (int i = 0; i < NTAG; i++)
#pragma unroll
        for (int j = 0; j < NTAG; j++)
            E[i][j] = __expf(sT[i * 11 + j]);

    // per-thread piece constants: piece f = tid + 128k covers seq f/9, 16B f%9
    int goff[9], tBk[9], doff[9];
#pragma unroll
    for (int k = 0; k < 9; k++) {
        const int f = tid + 128 * k;
        const int p = f / 9;
        const int q = f - 9 * p;
        goff[k] = sBase[p] + q * 4;     // float offset into bert (+ t0*9 later)
        tBk[k]  = stB[p];
        doff[k] = p * 36 + q * 4;       // float offset into stage
    }

    const unsigned sm0 = (unsigned)__cvta_generic_to_shared(dsm);
    auto issue = [&](int q) {          // predicated piece loads + commit (may be empty)
        const int t0 = t0s + 4 * q;
        const unsigned sb = sm0 + (unsigned)((q % STAGES) * STAGEF) * 4u;
#pragma unroll
        for (int k = 0; k < 9; k++) {
            if (t0 < tBk[k]) {
                const float* src = bert + goff[k] + t0 * 9;
                asm volatile("cp.async.ca.shared.global [%0], [%1], 16;"
                             :: "r"(sb + (unsigned)doff[k] * 4u), "l"(src));
            }
        }
        asm volatile("cp.async.commit_group;");
    };

    const int* tg = tags + (size_t)seq * SEQ;

    float W[NTAG];
    int   eAcc = 0, eRef = 0, prev = 0;
    float SRef = 0.0f, rg = 0.0f;
    const int gs = (c == 0) ? 1 : s;
    if (act && c > 0) {
#pragma unroll
        for (int j = 0; j < NTAG; j++) W[j] = 1.0f;
        prev = __ldg(tg + s - 1);
    }

    if (nq > 0) {
        issue(0);
        issue(1);
        int4 tq = __ldg(reinterpret_cast<const int4*>(tg + t0s));

        for (int q = 0; q < nq; ++q) {
            asm volatile("cp.async.wait_group 1;");
            __syncthreads();

            // own row-quad from smem (9x LDS.128, 4-way floor)
            float bq[36];
            const float* myq = dsm + (q % STAGES) * STAGEF + tid * 36;
#pragma unroll
            for (int k = 0; k < 9; k++) {
                const float4 v = *reinterpret_cast<const float4*>(myq + 4 * k);
                bq[4 * k + 0] = v.x; bq[4 * k + 1] = v.y;
                bq[4 * k + 2] = v.z; bq[4 * k + 3] = v.w;
            }
            const int tags4[4] = {tq.x, tq.y, tq.z, tq.w};
            if (q + 1 < nq)
                tq = __ldg(reinterpret_cast<const int4*>(tg + t0s + 4 * (q + 1)));

            issue(q + 2);   // stage (q+2)%3 == (q-1)%3: consumed before sync above

            const int t0 = t0s + 4 * q;
#pragma unroll
            for (int r = 0; r < 4; r++) {
                const int t = t0 + r;
                if (t < tB) {
                    if (t == 0) {
                        // exact init (c == 0 only)
#pragma unroll
                        for (int j = 0; j < NTAG; j++)
                            W[j] = __expf(sT[99 + j] + bq[4 * j + 0]);
                        prev = tags4[0];
                        float ev = bq[0];
#pragma unroll
                        for (int j = 1; j < NTAG; j++)
                            if (prev == j) ev = bq[4 * j + 0];
                        rg = sT[99 + prev] + ev;
                    } else {
                        // alpha update: W'_j = (sum_i W_i E_ij) * exp(em_tj)
                        float nw[NTAG];
#pragma unroll
                        for (int j = 0; j < NTAG; j++) {
                            float a = W[0] * E[0][j];
#pragma unroll
                            for (int i = 1; i < NTAG; i++) a = fmaf(W[i], E[i][j], a);
                            nw[j] = a * __expf(bq[4 * j + r]);
                        }
                        // exact power-of-2 rescale at t % 4 == 0
                        if (r == 0) {
                            float mx = nw[0];
#pragma unroll
                            for (int j = 1; j < NTAG; j++) mx = fmaxf(mx, nw[j]);
                            const int e = ((__float_as_int(mx) >> 23) & 255) - 127;
                            eAcc += e;
                            const float sc = __int_as_float((127 - e) << 23);
#pragma unroll
                            for (int j = 0; j < NTAG; j++) nw[j] *= sc;
                        }
#pragma unroll
                        for (int j = 0; j < NTAG; j++) W[j] = nw[j];

                        // reference point at end of warmup (c >= 1 only)
                        if (t == s - 1) {
                            eRef = eAcc;
                            float ss = W[0];
#pragma unroll
                            for (int j = 1; j < NTAG; j++) ss += W[j];
                            SRef = __logf(ss);
                        }
                        // gold path inside the window; emit from quad registers
                        if (t >= gs) {
                            const int tag = tags4[r];
                            float ev = bq[r];
#pragma unroll
                            for (int j = 1; j < NTAG; j++)
                                if (tag == j) ev = bq[4 * j + r];
                            rg += sT[prev * 11 + tag] + ev;
                            prev = tag;
                        }
                    }
                }
            }
        }
    }

    double contrib = 0.0;
    if (act) {
        const bool last = (L <= s + CL);       // chunk reaches t = L-1
        float r;
        if (last) {
            float fin = 0.0f;
#pragma unroll
            for (int j = 0; j < NTAG; j++)
                fin = fmaf(W[j], __expf(sT[j * 11 + 10]), fin);
            r  = 0.6931472f * (float)(eAcc - eRef) + __logf(fin) - SRef;
            rg += sT[prev * 11 + 10];
        } else {
            float ss = W[0];
#pragma unroll
            for (int j = 1; j < NTAG; j++) ss += W[j];
            r = 0.6931472f * (float)(eAcc - eRef) + __logf(ss) - SRef;
        }
        contrib = (double)r - (double)rg;
    }

    // warp reduce -> smem -> one global slot per CTA
#pragma unroll
    for (int o = 16; o; o >>= 1)
        contrib += __shfl_down_sync(0xffffffffu, contrib, o);
    if ((tid & 31) == 0) atomicAdd(&sAcc, contrib);
    __syncthreads();
    if (tid == 0) g_pacc[blockIdx.y * 32 + blockIdx.x] = sAcc;
}

// ============ 5) final reduction: partials + num_chars from g_len ============
__global__ void __launch_bounds__(128) crf_fin(float* out)
{
    __shared__ double    sa[128];
    __shared__ long long sc[128];
    const int tid = threadIdx.x;
    double a = 0.0;
    long long ch = 0;
    for (int i = tid; i < NPART; i += 128) a += g_pacc[i];
    for (int i = tid; i < BATCH; i += 128) ch += (long long)g_len[i];
    sa[tid] = a; sc[tid] = ch;
    __syncthreads();
    for (int o = 64; o; o >>= 1) {
        if (tid < o) { sa[tid] += sa[tid + o]; sc[tid] += sc[tid + o]; }
        __syncthreads();
    }
    if (tid == 0) out[0] = (float)(sa[0] / (double)sc[0]);
}

extern "C" void kernel_launch(void* const* d_in, const int* in_sizes, int n_in,
                              void* d_out, int out_size)
{
    const float* bert  = (const float*)d_in[0];
    const int*   mask  = (const int*)d_in[1];
    const int*   tags  = (const int*)d_in[2];
    const float* trans = (const float*)d_in[3];
    float* out = (float*)d_out;

    cudaFuncSetAttribute(crf_scan, cudaFuncAttributeMaxDynamicSharedMemorySize, DSMEM);

    crf_len_hist<<<BATCH / 4, 128>>>(mask);
    crf_prefix<<<1, 512>>>();
    crf_scatter<<<BATCH / 128, 128>>>();
    dim3 grid(32, NCHUNK);
    crf_scan<<<grid, 128, DSMEM>>>(bert, tags, trans);
    crf_fin<<<1, 128>>>(out);
}